// round 8
// baseline (speedup 1.0000x reference)
#include <cuda_runtime.h>

#define VQ_D 64
#define BLOCK_THREADS 256
#define MAX_BLOCKS 8192

typedef unsigned long long u64;

// Per-block partial sums of sum((quantized - x)^2); fixed-order reduced by kernel 2.
__device__ float g_vq_partials[MAX_BLOCKS];

// ---- packed f32x2 helpers (FFMA2 is only reachable via hand-written PTX) ----
__device__ __forceinline__ u64 fma2(u64 a, u64 b, u64 c) {
    u64 d;
    asm("fma.rn.f32x2 %0, %1, %2, %3;" : "=l"(d) : "l"(a), "l"(b), "l"(c));
    return d;
}
__device__ __forceinline__ u64 add2(u64 a, u64 b) {
    u64 d;
    asm("add.rn.f32x2 %0, %1, %2;" : "=l"(d) : "l"(a), "l"(b));
    return d;
}
__device__ __forceinline__ float2 u2f(u64 a) {
    float2 r;
    r.x = __uint_as_float((unsigned int)(a & 0xffffffffull));
    r.y = __uint_as_float((unsigned int)(a >> 32));
    return r;
}

// ---------------------------------------------------------------------------
// Main kernel: one thread = one x row. Codebook + per-code norms live in smem.
// dist_k = (||x||^2 + ||e_k||^2) - 2 * <x, e_k>   (matches reference rounding:
// the xx+ee add happens first, the 2*dot multiply and subtract are NOT fused).
// Argmin tie-break: strict '<' keeps the lowest index, matching jnp.argmin.
// ---------------------------------------------------------------------------
__global__ void __launch_bounds__(BLOCK_THREADS, 1)
vq_main_kernel(const float* __restrict__ x,
               const float* __restrict__ cb,
               float* __restrict__ out,
               int n, int K)
{
    extern __shared__ float sh[];
    float* sh_cb  = sh;                         // K * 64 floats
    float* sh_ee  = sh + (size_t)K * VQ_D;      // K floats
    float* sh_red = sh_ee + K;                  // 32 floats (block reduce)

    const int tid = threadIdx.x;

    // --- load codebook into shared (coalesced float4) ---
    {
        const float4* cb4 = (const float4*)cb;
        float4* sh4 = (float4*)sh_cb;
        const int total4 = K * VQ_D / 4;
        for (int i = tid; i < total4; i += BLOCK_THREADS) sh4[i] = cb4[i];
    }
    __syncthreads();

    // --- per-code squared norms (4 chains, near-pairwise accuracy) ---
    for (int kk = tid; kk < K; kk += BLOCK_THREADS) {
        const float* e = sh_cb + (size_t)kk * VQ_D;
        float a0 = 0.f, a1 = 0.f, a2 = 0.f, a3 = 0.f;
        #pragma unroll
        for (int j = 0; j < VQ_D; j += 4) {
            a0 = fmaf(e[j+0], e[j+0], a0);
            a1 = fmaf(e[j+1], e[j+1], a1);
            a2 = fmaf(e[j+2], e[j+2], a2);
            a3 = fmaf(e[j+3], e[j+3], a3);
        }
        sh_ee[kk] = __fadd_rn(__fadd_rn(a0, a1), __fadd_rn(a2, a3));
    }
    __syncthreads();

    const int row = blockIdx.x * BLOCK_THREADS + tid;
    float s_loss = 0.f;

    if (row < n) {
        // --- x row into registers as 32 packed f32x2 values ---
        u64 xr[VQ_D / 2];
        {
            const ulonglong2* xp = (const ulonglong2*)(x + (size_t)row * VQ_D);
            #pragma unroll
            for (int j = 0; j < VQ_D / 4; j++) {
                ulonglong2 v = xp[j];
                xr[2*j]   = v.x;
                xr[2*j+1] = v.y;
            }
        }

        // --- ||x||^2 ---
        float xx;
        {
            float a0 = 0.f, a1 = 0.f, a2 = 0.f, a3 = 0.f;
            #pragma unroll
            for (int j = 0; j < VQ_D / 2; j += 2) {
                float2 fa = u2f(xr[j]), fb = u2f(xr[j+1]);
                a0 = fmaf(fa.x, fa.x, a0);
                a1 = fmaf(fa.y, fa.y, a1);
                a2 = fmaf(fb.x, fb.x, a2);
                a3 = fmaf(fb.y, fb.y, a3);
            }
            xx = __fadd_rn(__fadd_rn(a0, a1), __fadd_rn(a2, a3));
        }

        // --- argmin over K codes ---
        float best = 3.402823466e38f;
        int   bi   = 0;
        const ulonglong2* ebase = (const ulonglong2*)sh_cb;

        #pragma unroll 2
        for (int kk = 0; kk < K; kk++) {
            const ulonglong2* e = ebase + (size_t)kk * (VQ_D / 4);
            u64 a0 = 0ull, a1 = 0ull, a2 = 0ull, a3 = 0ull;
            #pragma unroll
            for (int j = 0; j < VQ_D / 4; j += 2) {
                ulonglong2 e0 = e[j];
                ulonglong2 e1 = e[j + 1];
                a0 = fma2(e0.x, xr[2*j    ], a0);
                a1 = fma2(e0.y, xr[2*j + 1], a1);
                a2 = fma2(e1.x, xr[2*j + 2], a2);
                a3 = fma2(e1.y, xr[2*j + 3], a3);
            }
            u64 s = add2(add2(a0, a1), add2(a2, a3));
            float2 sf = u2f(s);
            float dot  = __fadd_rn(sf.x, sf.y);
            // (xx + ee) first, then subtract 2*dot WITHOUT fma contraction
            float dist = __fadd_rn(__fadd_rn(xx, sh_ee[kk]),
                                   -__fmul_rn(2.0f, dot));
            if (dist < best) { best = dist; bi = kk; }
        }

        // --- outputs: index (as float), quantized row, loss partial ---
        out[row] = (float)bi;

        const float*  e  = sh_cb + (size_t)bi * VQ_D;
        const float4* e4 = (const float4*)e;
        float4* q4 = (float4*)(out + (size_t)n + (size_t)row * VQ_D);
        #pragma unroll
        for (int j = 0; j < VQ_D / 4; j++) q4[j] = e4[j];

        float l0 = 0.f, l1 = 0.f, l2 = 0.f, l3 = 0.f;
        #pragma unroll
        for (int j2 = 0; j2 < VQ_D / 2; j2 += 2) {
            float2 fa = u2f(xr[j2]), fb = u2f(xr[j2 + 1]);
            float d0 = e[2*j2 + 0] - fa.x;
            float d1 = e[2*j2 + 1] - fa.y;
            float d2 = e[2*j2 + 2] - fb.x;
            float d3 = e[2*j2 + 3] - fb.y;
            l0 = fmaf(d0, d0, l0);
            l1 = fmaf(d1, d1, l1);
            l2 = fmaf(d2, d2, l2);
            l3 = fmaf(d3, d3, l3);
        }
        s_loss = __fadd_rn(__fadd_rn(l0, l1), __fadd_rn(l2, l3));
    }

    // --- deterministic block reduce of s_loss ---
    #pragma unroll
    for (int off = 16; off > 0; off >>= 1)
        s_loss += __shfl_down_sync(0xffffffffu, s_loss, off);
    if ((tid & 31) == 0) sh_red[tid >> 5] = s_loss;
    __syncthreads();
    if (tid == 0) {
        float t = 0.f;
        #pragma unroll
        for (int w = 0; w < BLOCK_THREADS / 32; w++) t += sh_red[w];
        g_vq_partials[blockIdx.x] = t;
    }
}

// ---------------------------------------------------------------------------
// Final deterministic reduction -> vq_loss = 1.25 * mean((q - x)^2)
// ---------------------------------------------------------------------------
__global__ void vq_reduce_kernel(float* __restrict__ out, int n, int nblocks)
{
    __shared__ double shd[BLOCK_THREADS];
    double s = 0.0;
    for (int i = threadIdx.x; i < nblocks; i += BLOCK_THREADS)
        s += (double)g_vq_partials[i];
    shd[threadIdx.x] = s;
    __syncthreads();
    for (int off = BLOCK_THREADS / 2; off > 0; off >>= 1) {
        if (threadIdx.x < off) shd[threadIdx.x] += shd[threadIdx.x + off];
        __syncthreads();
    }
    if (threadIdx.x == 0) {
        double mean = shd[0] / ((double)n * (double)VQ_D);
        out[(size_t)n + (size_t)n * VQ_D] = (float)(mean * 1.25);
    }
}

extern "C" void kernel_launch(void* const* d_in, const int* in_sizes, int n_in,
                              void* d_out, int out_size)
{
    const float* x  = (const float*)d_in[0];
    const float* cb = (const float*)d_in[1];
    float* out = (float*)d_out;

    const int n = in_sizes[0] / VQ_D;   // 524288
    const int K = in_sizes[1] / VQ_D;   // 512

    const int nblocks = (n + BLOCK_THREADS - 1) / BLOCK_THREADS;  // 2048
    const size_t smem = (size_t)K * VQ_D * sizeof(float)          // codebook
                      + (size_t)K * sizeof(float)                 // norms
                      + 64 * sizeof(float);                       // reduce pad

    cudaFuncSetAttribute(vq_main_kernel,
                         cudaFuncAttributeMaxDynamicSharedMemorySize,
                         (int)smem);

    vq_main_kernel<<<nblocks, BLOCK_THREADS, smem>>>(x, cb, out, n, K);
    vq_reduce_kernel<<<1, BLOCK_THREADS>>>(out, n, nblocks);
}

// round 9
// speedup vs baseline: 1.0007x; 1.0007x over previous
#include <cuda_runtime.h>

#define VQ_D 64
#define BLOCK_THREADS 256
#define MAX_BLOCKS 8192

typedef unsigned long long u64;

// Per-block partial sums of sum((quantized - x)^2); fixed-order reduced by kernel 2.
__device__ float g_vq_partials[MAX_BLOCKS];

// ---- packed f32x2 helpers (FFMA2 is only reachable via hand-written PTX) ----
__device__ __forceinline__ u64 fma2(u64 a, u64 b, u64 c) {
    u64 d;
    asm("fma.rn.f32x2 %0, %1, %2, %3;" : "=l"(d) : "l"(a), "l"(b), "l"(c));
    return d;
}
__device__ __forceinline__ u64 add2(u64 a, u64 b) {
    u64 d;
    asm("add.rn.f32x2 %0, %1, %2;" : "=l"(d) : "l"(a), "l"(b));
    return d;
}
__device__ __forceinline__ float2 u2f(u64 a) {
    float2 r;
    r.x = __uint_as_float((unsigned int)(a & 0xffffffffull));
    r.y = __uint_as_float((unsigned int)(a >> 32));
    return r;
}

// ---------------------------------------------------------------------------
// Main kernel: one thread = one x row. Codebook + per-code norms live in smem.
// dist_k = (||x||^2 + ||e_k||^2) - 2 * <x, e_k>   (matches reference rounding:
// the xx+ee add happens first, the 2*dot multiply and subtract are NOT fused).
// Argmin tie-break: strict '<' keeps the lowest index, matching jnp.argmin.
// ---------------------------------------------------------------------------
__global__ void __launch_bounds__(BLOCK_THREADS, 1)
vq_main_kernel(const float* __restrict__ x,
               const float* __restrict__ cb,
               float* __restrict__ out,
               int n, int K)
{
    extern __shared__ float sh[];
    float* sh_cb  = sh;                         // K * 64 floats
    float* sh_ee  = sh + (size_t)K * VQ_D;      // K floats
    float* sh_red = sh_ee + K;                  // 32 floats (block reduce)

    const int tid = threadIdx.x;

    // --- load codebook into shared (coalesced float4) ---
    {
        const float4* cb4 = (const float4*)cb;
        float4* sh4 = (float4*)sh_cb;
        const int total4 = K * VQ_D / 4;
        for (int i = tid; i < total4; i += BLOCK_THREADS) sh4[i] = cb4[i];
    }
    __syncthreads();

    // --- per-code squared norms (4 chains, near-pairwise accuracy) ---
    for (int kk = tid; kk < K; kk += BLOCK_THREADS) {
        const float* e = sh_cb + (size_t)kk * VQ_D;
        float a0 = 0.f, a1 = 0.f, a2 = 0.f, a3 = 0.f;
        #pragma unroll
        for (int j = 0; j < VQ_D; j += 4) {
            a0 = fmaf(e[j+0], e[j+0], a0);
            a1 = fmaf(e[j+1], e[j+1], a1);
            a2 = fmaf(e[j+2], e[j+2], a2);
            a3 = fmaf(e[j+3], e[j+3], a3);
        }
        sh_ee[kk] = __fadd_rn(__fadd_rn(a0, a1), __fadd_rn(a2, a3));
    }
    __syncthreads();

    const int row = blockIdx.x * BLOCK_THREADS + tid;
    float s_loss = 0.f;

    if (row < n) {
        // --- x row into registers as 32 packed f32x2 values ---
        u64 xr[VQ_D / 2];
        {
            const ulonglong2* xp = (const ulonglong2*)(x + (size_t)row * VQ_D);
            #pragma unroll
            for (int j = 0; j < VQ_D / 4; j++) {
                ulonglong2 v = xp[j];
                xr[2*j]   = v.x;
                xr[2*j+1] = v.y;
            }
        }

        // --- ||x||^2 ---
        float xx;
        {
            float a0 = 0.f, a1 = 0.f, a2 = 0.f, a3 = 0.f;
            #pragma unroll
            for (int j = 0; j < VQ_D / 2; j += 2) {
                float2 fa = u2f(xr[j]), fb = u2f(xr[j+1]);
                a0 = fmaf(fa.x, fa.x, a0);
                a1 = fmaf(fa.y, fa.y, a1);
                a2 = fmaf(fb.x, fb.x, a2);
                a3 = fmaf(fb.y, fb.y, a3);
            }
            xx = __fadd_rn(__fadd_rn(a0, a1), __fadd_rn(a2, a3));
        }

        // --- argmin over K codes ---
        float best = 3.402823466e38f;
        int   bi   = 0;
        const ulonglong2* ebase = (const ulonglong2*)sh_cb;

        #pragma unroll 2
        for (int kk = 0; kk < K; kk++) {
            const ulonglong2* e = ebase + (size_t)kk * (VQ_D / 4);
            u64 a0 = 0ull, a1 = 0ull, a2 = 0ull, a3 = 0ull;
            #pragma unroll
            for (int j = 0; j < VQ_D / 4; j += 2) {
                ulonglong2 e0 = e[j];
                ulonglong2 e1 = e[j + 1];
                a0 = fma2(e0.x, xr[2*j    ], a0);
                a1 = fma2(e0.y, xr[2*j + 1], a1);
                a2 = fma2(e1.x, xr[2*j + 2], a2);
                a3 = fma2(e1.y, xr[2*j + 3], a3);
            }
            u64 s = add2(add2(a0, a1), add2(a2, a3));
            float2 sf = u2f(s);
            float dot  = __fadd_rn(sf.x, sf.y);
            // (xx + ee) first, then subtract 2*dot WITHOUT fma contraction
            float dist = __fadd_rn(__fadd_rn(xx, sh_ee[kk]),
                                   -__fmul_rn(2.0f, dot));
            if (dist < best) { best = dist; bi = kk; }
        }

        // --- outputs: index (as float), quantized row, loss partial ---
        out[row] = (float)bi;

        const float*  e  = sh_cb + (size_t)bi * VQ_D;
        const float4* e4 = (const float4*)e;
        float4* q4 = (float4*)(out + (size_t)n + (size_t)row * VQ_D);
        #pragma unroll
        for (int j = 0; j < VQ_D / 4; j++) q4[j] = e4[j];

        float l0 = 0.f, l1 = 0.f, l2 = 0.f, l3 = 0.f;
        #pragma unroll
        for (int j2 = 0; j2 < VQ_D / 2; j2 += 2) {
            float2 fa = u2f(xr[j2]), fb = u2f(xr[j2 + 1]);
            float d0 = e[2*j2 + 0] - fa.x;
            float d1 = e[2*j2 + 1] - fa.y;
            float d2 = e[2*j2 + 2] - fb.x;
            float d3 = e[2*j2 + 3] - fb.y;
            l0 = fmaf(d0, d0, l0);
            l1 = fmaf(d1, d1, l1);
            l2 = fmaf(d2, d2, l2);
            l3 = fmaf(d3, d3, l3);
        }
        s_loss = __fadd_rn(__fadd_rn(l0, l1), __fadd_rn(l2, l3));
    }

    // --- deterministic block reduce of s_loss ---
    #pragma unroll
    for (int off = 16; off > 0; off >>= 1)
        s_loss += __shfl_down_sync(0xffffffffu, s_loss, off);
    if ((tid & 31) == 0) sh_red[tid >> 5] = s_loss;
    __syncthreads();
    if (tid == 0) {
        float t = 0.f;
        #pragma unroll
        for (int w = 0; w < BLOCK_THREADS / 32; w++) t += sh_red[w];
        g_vq_partials[blockIdx.x] = t;
    }
}

// ---------------------------------------------------------------------------
// Final deterministic reduction -> vq_loss = 1.25 * mean((q - x)^2)
// ---------------------------------------------------------------------------
__global__ void vq_reduce_kernel(float* __restrict__ out, int n, int nblocks)
{
    __shared__ double shd[BLOCK_THREADS];
    double s = 0.0;
    for (int i = threadIdx.x; i < nblocks; i += BLOCK_THREADS)
        s += (double)g_vq_partials[i];
    shd[threadIdx.x] = s;
    __syncthreads();
    for (int off = BLOCK_THREADS / 2; off > 0; off >>= 1) {
        if (threadIdx.x < off) shd[threadIdx.x] += shd[threadIdx.x + off];
        __syncthreads();
    }
    if (threadIdx.x == 0) {
        double mean = shd[0] / ((double)n * (double)VQ_D);
        out[(size_t)n + (size_t)n * VQ_D] = (float)(mean * 1.25);
    }
}

extern "C" void kernel_launch(void* const* d_in, const int* in_sizes, int n_in,
                              void* d_out, int out_size)
{
    const float* x  = (const float*)d_in[0];
    const float* cb = (const float*)d_in[1];
    float* out = (float*)d_out;

    const int n = in_sizes[0] / VQ_D;   // 524288
    const int K = in_sizes[1] / VQ_D;   // 512

    const int nblocks = (n + BLOCK_THREADS - 1) / BLOCK_THREADS;  // 2048
    const size_t smem = (size_t)K * VQ_D * sizeof(float)          // codebook
                      + (size_t)K * sizeof(float)                 // norms
                      + 64 * sizeof(float);                       // reduce pad

    cudaFuncSetAttribute(vq_main_kernel,
                         cudaFuncAttributeMaxDynamicSharedMemorySize,
                         (int)smem);

    vq_main_kernel<<<nblocks, BLOCK_THREADS, smem>>>(x, cb, out, n, K);
    vq_reduce_kernel<<<1, BLOCK_THREADS>>>(out, n, nblocks);
}

// round 10
// speedup vs baseline: 1.0920x; 1.0913x over previous
#include <cuda_runtime.h>

#define VQ_D 64
#define BLOCK_THREADS 512
#define MAX_BLOCKS 8192

typedef unsigned long long u64;

// Per-block partial sums of sum((quantized - x)^2); fixed-order reduced by kernel 2.
__device__ float g_vq_partials[MAX_BLOCKS];

// ---- packed f32x2 helpers (FFMA2 is only reachable via hand-written PTX) ----
__device__ __forceinline__ u64 fma2(u64 a, u64 b, u64 c) {
    u64 d;
    asm("fma.rn.f32x2 %0, %1, %2, %3;" : "=l"(d) : "l"(a), "l"(b), "l"(c));
    return d;
}
__device__ __forceinline__ u64 add2(u64 a, u64 b) {
    u64 d;
    asm("add.rn.f32x2 %0, %1, %2;" : "=l"(d) : "l"(a), "l"(b));
    return d;
}
__device__ __forceinline__ float2 u2f(u64 a) {
    float2 r;
    r.x = __uint_as_float((unsigned int)(a & 0xffffffffull));
    r.y = __uint_as_float((unsigned int)(a >> 32));
    return r;
}

// ---------------------------------------------------------------------------
// Main kernel: one thread = one x row. Codebook + per-code norms live in smem.
// dist_k = (||x||^2 + ||e_k||^2) - 2 * <x, e_k>   (matches reference rounding:
// the xx+ee add happens first, the 2*dot multiply and subtract are NOT fused).
// Argmin tie-break: strict '<' keeps the lowest index, matching jnp.argmin.
// 512 threads (16 warps, 4/SMSP) to hide LDS latency; still 1 block/SM (smem).
// ---------------------------------------------------------------------------
__global__ void __launch_bounds__(BLOCK_THREADS, 1)
vq_main_kernel(const float* __restrict__ x,
               const float* __restrict__ cb,
               float* __restrict__ out,
               int n, int K)
{
    extern __shared__ float sh[];
    float* sh_cb  = sh;                         // K * 64 floats
    float* sh_ee  = sh + (size_t)K * VQ_D;      // K floats
    float* sh_red = sh_ee + K;                  // 16 floats (block reduce)

    const int tid = threadIdx.x;

    // --- load codebook into shared (coalesced float4) ---
    {
        const float4* cb4 = (const float4*)cb;
        float4* sh4 = (float4*)sh_cb;
        const int total4 = K * VQ_D / 4;
        for (int i = tid; i < total4; i += BLOCK_THREADS) sh4[i] = cb4[i];
    }
    __syncthreads();

    // --- per-code squared norms (4 chains, near-pairwise accuracy) ---
    for (int kk = tid; kk < K; kk += BLOCK_THREADS) {
        const float* e = sh_cb + (size_t)kk * VQ_D;
        float a0 = 0.f, a1 = 0.f, a2 = 0.f, a3 = 0.f;
        #pragma unroll
        for (int j = 0; j < VQ_D; j += 4) {
            a0 = fmaf(e[j+0], e[j+0], a0);
            a1 = fmaf(e[j+1], e[j+1], a1);
            a2 = fmaf(e[j+2], e[j+2], a2);
            a3 = fmaf(e[j+3], e[j+3], a3);
        }
        sh_ee[kk] = __fadd_rn(__fadd_rn(a0, a1), __fadd_rn(a2, a3));
    }
    __syncthreads();

    const int row = blockIdx.x * BLOCK_THREADS + tid;
    float s_loss = 0.f;

    if (row < n) {
        // --- x row into registers as 32 packed f32x2 values ---
        u64 xr[VQ_D / 2];
        {
            const ulonglong2* xp = (const ulonglong2*)(x + (size_t)row * VQ_D);
            #pragma unroll
            for (int j = 0; j < VQ_D / 4; j++) {
                ulonglong2 v = xp[j];
                xr[2*j]   = v.x;
                xr[2*j+1] = v.y;
            }
        }

        // --- ||x||^2 ---
        float xx;
        {
            float a0 = 0.f, a1 = 0.f, a2 = 0.f, a3 = 0.f;
            #pragma unroll
            for (int j = 0; j < VQ_D / 2; j += 2) {
                float2 fa = u2f(xr[j]), fb = u2f(xr[j+1]);
                a0 = fmaf(fa.x, fa.x, a0);
                a1 = fmaf(fa.y, fa.y, a1);
                a2 = fmaf(fb.x, fb.x, a2);
                a3 = fmaf(fb.y, fb.y, a3);
            }
            xx = __fadd_rn(__fadd_rn(a0, a1), __fadd_rn(a2, a3));
        }

        // --- argmin over K codes (k processed in groups of 4; ee via float4) ---
        float best = 3.402823466e38f;
        int   bi   = 0;
        const ulonglong2* ebase = (const ulonglong2*)sh_cb;
        const float4*     ee4   = (const float4*)sh_ee;

        for (int kg = 0; kg < K / 4; kg++) {
            float4 eev = ee4[kg];
            #pragma unroll
            for (int ki = 0; ki < 4; ki++) {
                const int kk = kg * 4 + ki;
                const ulonglong2* e = ebase + (size_t)kk * (VQ_D / 4);
                u64 a0 = 0ull, a1 = 0ull, a2 = 0ull, a3 = 0ull;
                #pragma unroll
                for (int j = 0; j < VQ_D / 4; j += 2) {
                    ulonglong2 e0 = e[j];
                    ulonglong2 e1 = e[j + 1];
                    a0 = fma2(e0.x, xr[2*j    ], a0);
                    a1 = fma2(e0.y, xr[2*j + 1], a1);
                    a2 = fma2(e1.x, xr[2*j + 2], a2);
                    a3 = fma2(e1.y, xr[2*j + 3], a3);
                }
                u64 s = add2(add2(a0, a1), add2(a2, a3));
                float2 sf = u2f(s);
                float dot = __fadd_rn(sf.x, sf.y);
                float ee  = (ki == 0) ? eev.x : (ki == 1) ? eev.y
                          : (ki == 2) ? eev.z : eev.w;
                // (xx + ee) first, then subtract 2*dot WITHOUT fma contraction
                float dist = __fadd_rn(__fadd_rn(xx, ee),
                                       -__fmul_rn(2.0f, dot));
                if (dist < best) { best = dist; bi = kk; }
            }
        }

        // --- outputs: index (as float), quantized row, loss partial ---
        out[row] = (float)bi;

        const float*  e  = sh_cb + (size_t)bi * VQ_D;
        const float4* e4 = (const float4*)e;
        float4* q4 = (float4*)(out + (size_t)n + (size_t)row * VQ_D);
        #pragma unroll
        for (int j = 0; j < VQ_D / 4; j++) q4[j] = e4[j];

        float l0 = 0.f, l1 = 0.f, l2 = 0.f, l3 = 0.f;
        #pragma unroll
        for (int j2 = 0; j2 < VQ_D / 2; j2 += 2) {
            float2 fa = u2f(xr[j2]), fb = u2f(xr[j2 + 1]);
            float d0 = e[2*j2 + 0] - fa.x;
            float d1 = e[2*j2 + 1] - fa.y;
            float d2 = e[2*j2 + 2] - fb.x;
            float d3 = e[2*j2 + 3] - fb.y;
            l0 = fmaf(d0, d0, l0);
            l1 = fmaf(d1, d1, l1);
            l2 = fmaf(d2, d2, l2);
            l3 = fmaf(d3, d3, l3);
        }
        s_loss = __fadd_rn(__fadd_rn(l0, l1), __fadd_rn(l2, l3));
    }

    // --- deterministic block reduce of s_loss ---
    #pragma unroll
    for (int off = 16; off > 0; off >>= 1)
        s_loss += __shfl_down_sync(0xffffffffu, s_loss, off);
    if ((tid & 31) == 0) sh_red[tid >> 5] = s_loss;
    __syncthreads();
    if (tid == 0) {
        float t = 0.f;
        #pragma unroll
        for (int w = 0; w < BLOCK_THREADS / 32; w++) t += sh_red[w];
        g_vq_partials[blockIdx.x] = t;
    }
}

// ---------------------------------------------------------------------------
// Final deterministic reduction -> vq_loss = 1.25 * mean((q - x)^2)
// ---------------------------------------------------------------------------
__global__ void vq_reduce_kernel(float* __restrict__ out, int n, int nblocks)
{
    __shared__ double shd[256];
    double s = 0.0;
    for (int i = threadIdx.x; i < nblocks; i += 256)
        s += (double)g_vq_partials[i];
    shd[threadIdx.x] = s;
    __syncthreads();
    for (int off = 128; off > 0; off >>= 1) {
        if (threadIdx.x < off) shd[threadIdx.x] += shd[threadIdx.x + off];
        __syncthreads();
    }
    if (threadIdx.x == 0) {
        double mean = shd[0] / ((double)n * (double)VQ_D);
        out[(size_t)n + (size_t)n * VQ_D] = (float)(mean * 1.25);
    }
}

extern "C" void kernel_launch(void* const* d_in, const int* in_sizes, int n_in,
                              void* d_out, int out_size)
{
    const float* x  = (const float*)d_in[0];
    const float* cb = (const float*)d_in[1];
    float* out = (float*)d_out;

    const int n = in_sizes[0] / VQ_D;   // 524288
    const int K = in_sizes[1] / VQ_D;   // 512

    const int nblocks = (n + BLOCK_THREADS - 1) / BLOCK_THREADS;  // 1024
    const size_t smem = (size_t)K * VQ_D * sizeof(float)          // codebook
                      + (size_t)K * sizeof(float)                 // norms
                      + 64 * sizeof(float);                       // reduce pad

    cudaFuncSetAttribute(vq_main_kernel,
                         cudaFuncAttributeMaxDynamicSharedMemorySize,
                         (int)smem);

    vq_main_kernel<<<nblocks, BLOCK_THREADS, smem>>>(x, cb, out, n, K);
    vq_reduce_kernel<<<1, 256>>>(out, n, nblocks);
}

// round 12
// speedup vs baseline: 2.3774x; 2.1770x over previous
#include <cuda_runtime.h>
#include <cuda_fp16.h>
#include <float.h>

#define VQ_D      64
#define KCODES    512
#define M_TILE    128
#define NTHREADS  256
#define NROWS_MAX 524288
#define TAU       1e-3f

typedef unsigned int       u32;
typedef unsigned long long u64;

// ---------------- global scratch (static: no allocation) ----------------
__device__ int    g_flag_count;
__device__ int    g_flag_rows[NROWS_MAX];
__device__ float  g_loss_row[NROWS_MAX];
__device__ double g_partials[256];

// ---------------- smem layout of main kernel (bytes) ----------------
#define SM_BHI   0                       // 512*128 = 65536  B hi fp16, SW128
#define SM_BLO   (SM_BHI + KCODES*128)   // 65536
#define SM_AHI   (SM_BLO + KCODES*128)   // 131072  128*128
#define SM_ALO   (SM_AHI + M_TILE*128)   // 147456
#define SM_EE    (SM_ALO + M_TILE*128)   // 163840  512 f32
#define SM_XX    (SM_EE  + KCODES*4)     // 165888  128 f32
#define SM_XXP   (SM_XX  + M_TILE*4)     // 166400  256 f32
#define SM_SB    (SM_XXP + 2*M_TILE*4)   // 167424  2*128 f32 best
#define SM_SS    (SM_SB  + 2*M_TILE*4)   // 168448  2*128 f32 second
#define SM_SI    (SM_SS  + 2*M_TILE*4)   // 169472  2*128 i32 idx
#define SM_TOTAL (SM_SI  + 2*M_TILE*4 + 64)

// ---------------- helpers ----------------
__device__ __forceinline__ u32 smem_u32_base(const void* p) {
    u32 a;
    asm("{ .reg .u64 t; cvta.to.shared.u64 t, %1; cvt.u32.u64 %0, t; }"
        : "=r"(a) : "l"(p));
    return a;
}
// swizzled byte offset for 128B-row tiles (SW128: bits[6:4] ^= bits[9:7])
__device__ __forceinline__ u32 swofs(u32 row, u32 off) {
    u32 b = row * 128u + off;
    return b ^ ((b >> 3) & 0x70u);
}
__device__ __forceinline__ void ldsm_x4(u32& r0, u32& r1, u32& r2, u32& r3, u32 addr) {
    asm volatile("ldmatrix.sync.aligned.m8n8.x4.shared.b16 {%0,%1,%2,%3}, [%4];"
        : "=r"(r0), "=r"(r1), "=r"(r2), "=r"(r3) : "r"(addr));
}
__device__ __forceinline__ void mma16816(float* c, const u32* a, u32 b0, u32 b1) {
    asm volatile("mma.sync.aligned.m16n8k16.row.col.f32.f16.f16.f32 "
        "{%0,%1,%2,%3}, {%4,%5,%6,%7}, {%8,%9}, {%0,%1,%2,%3};"
        : "+f"(c[0]), "+f"(c[1]), "+f"(c[2]), "+f"(c[3])
        : "r"(a[0]), "r"(a[1]), "r"(a[2]), "r"(a[3]), "r"(b0), "r"(b1));
}
// fp16 Dekker split: v = (float)hi + (float)lo + O(2^-22 |v|)
__device__ __forceinline__ void split16(float v, __half& hi, __half& lo) {
    hi = __float2half_rn(v);
    lo = __float2half_rn(v - __half2float(hi));
}
// packed f32x2 (exact replica of the R8 arithmetic for the fixup path)
__device__ __forceinline__ u64 fma2(u64 a, u64 b, u64 c) {
    u64 d;
    asm("fma.rn.f32x2 %0, %1, %2, %3;" : "=l"(d) : "l"(a), "l"(b), "l"(c));
    return d;
}
__device__ __forceinline__ u64 add2(u64 a, u64 b) {
    u64 d;
    asm("add.rn.f32x2 %0, %1, %2;" : "=l"(d) : "l"(a), "l"(b));
    return d;
}
__device__ __forceinline__ float2 u2f(u64 a) {
    float2 r;
    r.x = __uint_as_float((unsigned int)(a & 0xffffffffull));
    r.y = __uint_as_float((unsigned int)(a >> 32));
    return r;
}

// ---------------------------------------------------------------------------
// Kernel 0: reset flag counter
// ---------------------------------------------------------------------------
__global__ void vq_init_kernel() { g_flag_count = 0; }

// ---------------------------------------------------------------------------
// Kernel 1: tensor-core distance pass (fp16 split, 3 terms) + margin flagging
// ---------------------------------------------------------------------------
__global__ void __launch_bounds__(NTHREADS, 1)
vq_main_kernel(const float* __restrict__ x,
               const float* __restrict__ cb,
               float* __restrict__ out,
               int n)
{
    extern __shared__ char sm[];
    const u32 su  = smem_u32_base(sm);
    const int tid = threadIdx.x;
    const int w   = tid >> 5;
    const int lid = tid & 31;
    const int wm  = w & 3;        // M chunk: rows wm*32..+32
    const int wn  = w >> 2;       // N half:  codes wn*256..+256

    float* sh_ee  = (float*)(sm + SM_EE);
    float* sh_xx  = (float*)(sm + SM_XX);
    float* sh_xxp = (float*)(sm + SM_XXP);
    float* sh_b   = (float*)(sm + SM_SB);
    float* sh_s   = (float*)(sm + SM_SS);
    int*   sh_i   = (int*)  (sm + SM_SI);

    // ---- codebook: split into B_hi/B_lo fp16 (SW128) + fp32 ||e||^2 ----
    for (int kk = tid; kk < KCODES; kk += NTHREADS) {
        const float4* e4 = (const float4*)(cb + (size_t)kk * VQ_D);
        float a0 = 0.f, a1 = 0.f, a2 = 0.f, a3 = 0.f;
        #pragma unroll
        for (int j = 0; j < 16; j++) {
            float4 v = e4[j];
            __half h0, h1, h2, h3, l0h, l1h, l2h, l3h;
            split16(v.x, h0, l0h); split16(v.y, h1, l1h);
            split16(v.z, h2, l2h); split16(v.w, h3, l3h);
            u32 b = swofs((u32)kk, (u32)j * 8u);
            *(__half2*)(sm + SM_BHI + b)     = __halves2half2(h0, h1);
            *(__half2*)(sm + SM_BHI + b + 4) = __halves2half2(h2, h3);
            *(__half2*)(sm + SM_BLO + b)     = __halves2half2(l0h, l1h);
            *(__half2*)(sm + SM_BLO + b + 4) = __halves2half2(l2h, l3h);
            a0 = fmaf(v.x, v.x, a0); a1 = fmaf(v.y, v.y, a1);
            a2 = fmaf(v.z, v.z, a2); a3 = fmaf(v.w, v.w, a3);
        }
        sh_ee[kk] = __fadd_rn(__fadd_rn(a0, a1), __fadd_rn(a2, a3));
    }
    __syncthreads();

    // per-lane ldmatrix address components
    const u32 arow = (u32)(lid & 7) + ((u32)(lid >> 3) & 1u) * 8u;
    const u32 aoff = ((u32)(lid >> 4) & 1u) * 16u;
    const u32 brow = (u32)(lid & 7) + ((u32)(lid >> 4) & 1u) * 8u;
    const u32 boff = ((u32)(lid >> 3) & 1u) * 16u;
    const int g = lid >> 2, t = lid & 3;

    const int ntiles = n / M_TILE;

    for (int tile = blockIdx.x; tile < ntiles; tile += gridDim.x) {
        // ---- load + split x tile: thread -> row tid/2, d-half tid&1 ----
        {
            const int r = tid >> 1, h = tid & 1;
            const float4* xp = (const float4*)(x + ((size_t)tile * M_TILE + r) * VQ_D + h * 32);
            float p0 = 0.f, p1 = 0.f, p2 = 0.f, p3 = 0.f;
            #pragma unroll
            for (int j = 0; j < 8; j++) {
                float4 v = xp[j];
                __half h0, h1, h2, h3, l0h, l1h, l2h, l3h;
                split16(v.x, h0, l0h); split16(v.y, h1, l1h);
                split16(v.z, h2, l2h); split16(v.w, h3, l3h);
                u32 b = swofs((u32)r, (u32)(h * 64 + j * 8));
                *(__half2*)(sm + SM_AHI + b)     = __halves2half2(h0, h1);
                *(__half2*)(sm + SM_AHI + b + 4) = __halves2half2(h2, h3);
                *(__half2*)(sm + SM_ALO + b)     = __halves2half2(l0h, l1h);
                *(__half2*)(sm + SM_ALO + b + 4) = __halves2half2(l2h, l3h);
                p0 = fmaf(v.x, v.x, p0); p1 = fmaf(v.y, v.y, p1);
                p2 = fmaf(v.z, v.z, p2); p3 = fmaf(v.w, v.w, p3);
            }
            sh_xxp[h * M_TILE + r] = __fadd_rn(__fadd_rn(p0, p1), __fadd_rn(p2, p3));
        }
        __syncthreads();
        if (tid < M_TILE)
            sh_xx[tid] = __fadd_rn(sh_xxp[tid], sh_xxp[M_TILE + tid]);
        __syncthreads();

        // ---- A fragments for this warp's 32 rows (hi & lo), all 4 k-chunks ----
        u32 ahi[2][4][4], alo[2][4][4];
        #pragma unroll
        for (int ms = 0; ms < 2; ms++) {
            #pragma unroll
            for (int k = 0; k < 4; k++) {
                u32 o = swofs((u32)(wm * 32 + ms * 16) + arow, (u32)k * 32u + aoff);
                ldsm_x4(ahi[ms][k][0], ahi[ms][k][1], ahi[ms][k][2], ahi[ms][k][3],
                        su + SM_AHI + o);
                ldsm_x4(alo[ms][k][0], alo[ms][k][1], alo[ms][k][2], alo[ms][k][3],
                        su + SM_ALO + o);
            }
        }

        float xx0 = sh_xx[wm * 32 + g];
        float xx1 = sh_xx[wm * 32 + g + 8];
        float xx2 = sh_xx[wm * 32 + 16 + g];
        float xx3 = sh_xx[wm * 32 + 24 + g];

        float best[4] = {FLT_MAX, FLT_MAX, FLT_MAX, FLT_MAX};
        float sec [4] = {FLT_MAX, FLT_MAX, FLT_MAX, FLT_MAX};
        int   bidx[4] = {0, 0, 0, 0};

        #pragma unroll 1
        for (int chunk = 0; chunk < 4; chunk++) {
            const int nbase = wn * 256 + chunk * 64;
            float acc[2][8][4];
            #pragma unroll
            for (int ms = 0; ms < 2; ms++)
                #pragma unroll
                for (int j = 0; j < 8; j++)
                    #pragma unroll
                    for (int q = 0; q < 4; q++) acc[ms][j][q] = 0.f;

            #pragma unroll
            for (int k = 0; k < 4; k++) {
                u32 bh0[8], bh1[8], bl0[8], bl1[8];
                #pragma unroll
                for (int gi = 0; gi < 4; gi++) {
                    u32 o = swofs((u32)(nbase + gi * 16) + brow, (u32)k * 32u + boff);
                    ldsm_x4(bh0[2*gi], bh1[2*gi], bh0[2*gi+1], bh1[2*gi+1], su + SM_BHI + o);
                    ldsm_x4(bl0[2*gi], bl1[2*gi], bl0[2*gi+1], bl1[2*gi+1], su + SM_BLO + o);
                }
                #pragma unroll
                for (int ms = 0; ms < 2; ms++) {
                    #pragma unroll
                    for (int j = 0; j < 8; j++) {
                        mma16816(acc[ms][j], ahi[ms][k], bh0[j], bh1[j]);  // hi*hi
                        mma16816(acc[ms][j], alo[ms][k], bh0[j], bh1[j]);  // lo*hi
                        mma16816(acc[ms][j], ahi[ms][k], bl0[j], bl1[j]);  // hi*lo
                    }
                }
            }

            // ---- epilogue: distances + top-2 tracking ----
            #pragma unroll
            for (int ms = 0; ms < 2; ms++) {
                const float xa = (ms == 0) ? xx0 : xx2;
                const float xb = (ms == 0) ? xx1 : xx3;
                const int ri = ms * 2;
                #pragma unroll
                for (int j = 0; j < 8; j++) {
                    const int c0 = nbase + j * 8 + 2 * t;
                    float2 ee = *(const float2*)(&sh_ee[c0]);
                    float d00 = fmaf(acc[ms][j][0], -2.f, xa + ee.x);
                    float d01 = fmaf(acc[ms][j][1], -2.f, xa + ee.y);
                    float d10 = fmaf(acc[ms][j][2], -2.f, xb + ee.x);
                    float d11 = fmaf(acc[ms][j][3], -2.f, xb + ee.y);
                    #define UPD(r_, d_, c_) \
                        if ((d_) < best[r_]) { sec[r_] = best[r_]; best[r_] = (d_); bidx[r_] = (c_); } \
                        else sec[r_] = fminf(sec[r_], (d_));
                    UPD(ri,     d00, c0); UPD(ri,     d01, c0 + 1);
                    UPD(ri + 1, d10, c0); UPD(ri + 1, d11, c0 + 1);
                    #undef UPD
                }
            }
        }

        // ---- intra-warp merge over the 4 t-lanes sharing each row ----
        #pragma unroll
        for (int off = 1; off <= 2; off <<= 1) {
            #pragma unroll
            for (int ri = 0; ri < 4; ri++) {
                float ob = __shfl_xor_sync(0xffffffffu, best[ri], off);
                float os = __shfl_xor_sync(0xffffffffu, sec[ri],  off);
                int   oi = __shfl_xor_sync(0xffffffffu, bidx[ri], off);
                bool take = (ob < best[ri]) || (ob == best[ri] && oi < bidx[ri]);
                float loser = take ? best[ri] : ob;
                sec[ri] = fminf(loser, fminf(sec[ri], os));
                if (take) { best[ri] = ob; bidx[ri] = oi; }
            }
        }
        if (t == 0) {
            const int r0 = wm * 32 + g;
            const int rows[4] = {r0, r0 + 8, r0 + 16, r0 + 24};
            #pragma unroll
            for (int ri = 0; ri < 4; ri++) {
                sh_b[wn * M_TILE + rows[ri]] = best[ri];
                sh_s[wn * M_TILE + rows[ri]] = sec[ri];
                sh_i[wn * M_TILE + rows[ri]] = bidx[ri];
            }
        }
        __syncthreads();

        // ---- combine halves, flag near-ties, write outputs ----
        if (tid < M_TILE) {
            float b0 = sh_b[tid], b1 = sh_b[M_TILE + tid];
            float s0 = sh_s[tid], s1 = sh_s[M_TILE + tid];
            int   i0 = sh_i[tid], i1 = sh_i[M_TILE + tid];
            bool take = (b1 < b0) || (b1 == b0 && i1 < i0);
            float fb = take ? b1 : b0;
            int   fi = take ? i1 : i0;
            float fs = fminf(take ? b0 : b1, fminf(s0, s1));

            const size_t grow = (size_t)tile * M_TILE + tid;
            if (fs - fb < TAU) {
                int p = atomicAdd(&g_flag_count, 1);
                g_flag_rows[p] = (int)grow;
            }
            out[grow] = (float)fi;

            const float4* e4  = (const float4*)(cb + (size_t)fi * VQ_D);
            const float4* xr4 = (const float4*)(x + grow * VQ_D);
            float4* q4 = (float4*)(out + (size_t)n + grow * VQ_D);
            float l0 = 0.f, l1 = 0.f, l2 = 0.f, l3 = 0.f;
            #pragma unroll
            for (int j = 0; j < 16; j++) {
                float4 e = e4[j], xv = xr4[j];
                q4[j] = e;
                float d0 = e.x - xv.x, d1 = e.y - xv.y;
                float d2 = e.z - xv.z, d3 = e.w - xv.w;
                l0 = fmaf(d0, d0, l0); l1 = fmaf(d1, d1, l1);
                l2 = fmaf(d2, d2, l2); l3 = fmaf(d3, d3, l3);
            }
            g_loss_row[grow] = __fadd_rn(__fadd_rn(l0, l1), __fadd_rn(l2, l3));
        }
        __syncthreads();   // outputs done before A smem is overwritten
    }
}

// ---------------------------------------------------------------------------
// Kernel 2: exact fp32 fixup of flagged rows (bit-identical to the R8 kernel
// arithmetic that passed with zero argmin flips)
// ---------------------------------------------------------------------------
__global__ void __launch_bounds__(256, 1)
vq_fixup_kernel(const float* __restrict__ x,
                const float* __restrict__ cb,
                float* __restrict__ out,
                int n)
{
    if (*(volatile int*)&g_flag_count == 0) return;

    extern __shared__ float sh[];
    float* sh_cb = sh;                 // 512*64
    float* sh_ee = sh + KCODES * VQ_D; // 512

    const int tid = threadIdx.x;
    {
        const float4* cb4 = (const float4*)cb;
        float4* sh4 = (float4*)sh_cb;
        for (int i = tid; i < KCODES * VQ_D / 4; i += 256) sh4[i] = cb4[i];
    }
    __syncthreads();
    for (int kk = tid; kk < KCODES; kk += 256) {
        const float* e = sh_cb + (size_t)kk * VQ_D;
        float a0 = 0.f, a1 = 0.f, a2 = 0.f, a3 = 0.f;
        #pragma unroll
        for (int j = 0; j < VQ_D; j += 4) {
            a0 = fmaf(e[j+0], e[j+0], a0);
            a1 = fmaf(e[j+1], e[j+1], a1);
            a2 = fmaf(e[j+2], e[j+2], a2);
            a3 = fmaf(e[j+3], e[j+3], a3);
        }
        sh_ee[kk] = __fadd_rn(__fadd_rn(a0, a1), __fadd_rn(a2, a3));
    }
    __syncthreads();

    const int count = g_flag_count;
    for (int i = blockIdx.x * 256 + tid; i < count; i += gridDim.x * 256) {
        const int row = g_flag_rows[i];

        u64 xr[VQ_D / 2];
        const ulonglong2* xp = (const ulonglong2*)(x + (size_t)row * VQ_D);
        #pragma unroll
        for (int j = 0; j < VQ_D / 4; j++) {
            ulonglong2 v = xp[j];
            xr[2*j] = v.x; xr[2*j+1] = v.y;
        }
        float xx;
        {
            float a0 = 0.f, a1 = 0.f, a2 = 0.f, a3 = 0.f;
            #pragma unroll
            for (int j = 0; j < VQ_D / 2; j += 2) {
                float2 fa = u2f(xr[j]), fb = u2f(xr[j+1]);
                a0 = fmaf(fa.x, fa.x, a0); a1 = fmaf(fa.y, fa.y, a1);
                a2 = fmaf(fb.x, fb.x, a2); a3 = fmaf(fb.y, fb.y, a3);
            }
            xx = __fadd_rn(__fadd_rn(a0, a1), __fadd_rn(a2, a3));
        }

        float best = 3.402823466e38f;
        int   bi   = 0;
        const ulonglong2* ebase = (const ulonglong2*)sh_cb;
        #pragma unroll 2
        for (int kk = 0; kk < KCODES; kk++) {
            const ulonglong2* e = ebase + (size_t)kk * (VQ_D / 4);
            u64 a0 = 0ull, a1 = 0ull, a2 = 0ull, a3 = 0ull;
            #pragma unroll
            for (int j = 0; j < VQ_D / 4; j += 2) {
                ulonglong2 e0 = e[j];
                ulonglong2 e1 = e[j + 1];
                a0 = fma2(e0.x, xr[2*j    ], a0);
                a1 = fma2(e0.y, xr[2*j + 1], a1);
                a2 = fma2(e1.x, xr[2*j + 2], a2);
                a3 = fma2(e1.y, xr[2*j + 3], a3);
            }
            u64 s = add2(add2(a0, a1), add2(a2, a3));
            float2 sf = u2f(s);
            float dot  = __fadd_rn(sf.x, sf.y);
            float dist = __fadd_rn(__fadd_rn(xx, sh_ee[kk]),
                                   -__fmul_rn(2.0f, dot));
            if (dist < best) { best = dist; bi = kk; }
        }

        out[row] = (float)bi;
        const float*  e  = sh_cb + (size_t)bi * VQ_D;
        const float4* e4 = (const float4*)e;
        float4* q4 = (float4*)(out + (size_t)n + (size_t)row * VQ_D);
        #pragma unroll
        for (int j = 0; j < VQ_D / 4; j++) q4[j] = e4[j];

        float l0 = 0.f, l1 = 0.f, l2 = 0.f, l3 = 0.f;
        #pragma unroll
        for (int j2 = 0; j2 < VQ_D / 2; j2 += 2) {
            float2 fa = u2f(xr[j2]), fb = u2f(xr[j2 + 1]);
            float d0 = e[2*j2 + 0] - fa.x;
            float d1 = e[2*j2 + 1] - fa.y;
            float d2 = e[2*j2 + 2] - fb.x;
            float d3 = e[2*j2 + 3] - fb.y;
            l0 = fmaf(d0, d0, l0); l1 = fmaf(d1, d1, l1);
            l2 = fmaf(d2, d2, l2); l3 = fmaf(d3, d3, l3);
        }
        g_loss_row[row] = __fadd_rn(__fadd_rn(l0, l1), __fadd_rn(l2, l3));
    }
}

// ---------------------------------------------------------------------------
// Kernels 3+4: deterministic staged loss reduction
// ---------------------------------------------------------------------------
__global__ void vq_reduceA_kernel(int n)
{
    __shared__ double shd[256];
    const int base = blockIdx.x * 2048;
    double s = 0.0;
    #pragma unroll
    for (int j = 0; j < 8; j++) {
        int idx = base + j * 256 + threadIdx.x;
        s += (idx < n) ? (double)g_loss_row[idx] : 0.0;
    }
    shd[threadIdx.x] = s;
    __syncthreads();
    for (int off = 128; off > 0; off >>= 1) {
        if (threadIdx.x < off) shd[threadIdx.x] += shd[threadIdx.x + off];
        __syncthreads();
    }
    if (threadIdx.x == 0) g_partials[blockIdx.x] = shd[0];
}

__global__ void vq_reduceB_kernel(float* __restrict__ out, int n)
{
    __shared__ double shd[256];
    shd[threadIdx.x] = g_partials[threadIdx.x];
    __syncthreads();
    for (int off = 128; off > 0; off >>= 1) {
        if (threadIdx.x < off) shd[threadIdx.x] += shd[threadIdx.x + off];
        __syncthreads();
    }
    if (threadIdx.x == 0) {
        double mean = shd[0] / ((double)n * (double)VQ_D);
        out[(size_t)n + (size_t)n * VQ_D] = (float)(mean * 1.25);
    }
}

// ---------------------------------------------------------------------------
extern "C" void kernel_launch(void* const* d_in, const int* in_sizes, int n_in,
                              void* d_out, int out_size)
{
    const float* x  = (const float*)d_in[0];
    const float* cb = (const float*)d_in[1];
    float* out = (float*)d_out;

    const int n = in_sizes[0] / VQ_D;      // 524288
    const int ntiles = n / M_TILE;         // 4096
    int grid = ntiles < 148 ? ntiles : 148;

    static int attr_done = 0;
    if (!attr_done) {
        cudaFuncSetAttribute(vq_main_kernel,
                             cudaFuncAttributeMaxDynamicSharedMemorySize, SM_TOTAL);
        cudaFuncSetAttribute(vq_fixup_kernel,
                             cudaFuncAttributeMaxDynamicSharedMemorySize,
                             (KCODES * VQ_D + KCODES) * 4);
        attr_done = 1;
    }

    vq_init_kernel<<<1, 1>>>();
    vq_main_kernel<<<grid, NTHREADS, SM_TOTAL>>>(x, cb, out, n);
    vq_fixup_kernel<<<64, 256, (KCODES * VQ_D + KCODES) * 4>>>(x, cb, out, n);
    vq_reduceA_kernel<<<256, 256>>>(n);
    vq_reduceB_kernel<<<1, 256>>>(out, n);
}

// round 13
// speedup vs baseline: 2.3846x; 1.0030x over previous
#include <cuda_runtime.h>
#include <cuda_fp16.h>
#include <float.h>

#define VQ_D      64
#define KCODES    512
#define M_TILE    128
#define NTHREADS  256
#define NROWS_MAX 524288
#define TAU       1e-3f

typedef unsigned int       u32;
typedef unsigned long long u64;

// ---------------- global scratch (static: no allocation) ----------------
__device__ int    g_flag_count;
__device__ int    g_flag_rows[NROWS_MAX];
__device__ float  g_loss_row[NROWS_MAX];
__device__ double g_partials[256];

// ---------------- smem layout of main kernel (bytes) ----------------
#define SM_BHI   0                       // 512*128 = 65536  B hi fp16, SW128
#define SM_BLO   (SM_BHI + KCODES*128)   // 65536
#define SM_AHI   (SM_BLO + KCODES*128)   // 131072  128*128
#define SM_ALO   (SM_AHI + M_TILE*128)   // 147456
#define SM_EE    (SM_ALO + M_TILE*128)   // 163840  512 f32
#define SM_XX    (SM_EE  + KCODES*4)     // 165888  128 f32
#define SM_XXP   (SM_XX  + M_TILE*4)     // 166400  256 f32
#define SM_SB    (SM_XXP + 2*M_TILE*4)   // 167424  2*128 f32 best
#define SM_SS    (SM_SB  + 2*M_TILE*4)   // 168448  2*128 f32 second
#define SM_SI    (SM_SS  + 2*M_TILE*4)   // 169472  2*128 i32 idx
#define SM_TOTAL (SM_SI  + 2*M_TILE*4 + 64)

// ---------------- helpers ----------------
__device__ __forceinline__ u32 smem_u32_base(const void* p) {
    u32 a;
    asm("{ .reg .u64 t; cvta.to.shared.u64 t, %1; cvt.u32.u64 %0, t; }"
        : "=r"(a) : "l"(p));
    return a;
}
// swizzled byte offset for 128B-row tiles (SW128: bits[6:4] ^= bits[9:7])
__device__ __forceinline__ u32 swofs(u32 row, u32 off) {
    u32 b = row * 128u + off;
    return b ^ ((b >> 3) & 0x70u);
}
__device__ __forceinline__ void ldsm_x4(u32& r0, u32& r1, u32& r2, u32& r3, u32 addr) {
    asm volatile("ldmatrix.sync.aligned.m8n8.x4.shared.b16 {%0,%1,%2,%3}, [%4];"
        : "=r"(r0), "=r"(r1), "=r"(r2), "=r"(r3) : "r"(addr));
}
__device__ __forceinline__ void mma16816(float* c, const u32* a, u32 b0, u32 b1) {
    asm volatile("mma.sync.aligned.m16n8k16.row.col.f32.f16.f16.f32 "
        "{%0,%1,%2,%3}, {%4,%5,%6,%7}, {%8,%9}, {%0,%1,%2,%3};"
        : "+f"(c[0]), "+f"(c[1]), "+f"(c[2]), "+f"(c[3])
        : "r"(a[0]), "r"(a[1]), "r"(a[2]), "r"(a[3]), "r"(b0), "r"(b1));
}
// fp16 Dekker split: v = (float)hi + (float)lo + O(2^-22 |v|)
__device__ __forceinline__ void split16(float v, __half& hi, __half& lo) {
    hi = __float2half_rn(v);
    lo = __float2half_rn(v - __half2float(hi));
}
// packed f32x2 (exact replica of the R8 arithmetic for the fixup path)
__device__ __forceinline__ u64 fma2(u64 a, u64 b, u64 c) {
    u64 d;
    asm("fma.rn.f32x2 %0, %1, %2, %3;" : "=l"(d) : "l"(a), "l"(b), "l"(c));
    return d;
}
__device__ __forceinline__ u64 add2(u64 a, u64 b) {
    u64 d;
    asm("add.rn.f32x2 %0, %1, %2;" : "=l"(d) : "l"(a), "l"(b));
    return d;
}
__device__ __forceinline__ float2 u2f(u64 a) {
    float2 r;
    r.x = __uint_as_float((unsigned int)(a & 0xffffffffull));
    r.y = __uint_as_float((unsigned int)(a >> 32));
    return r;
}

// ---------------------------------------------------------------------------
// Kernel 0: reset flag counter
// ---------------------------------------------------------------------------
__global__ void vq_init_kernel() { g_flag_count = 0; }

// ---------------------------------------------------------------------------
// Kernel 1: tensor-core distance pass (fp16 split, 3 terms) + margin flagging
// ---------------------------------------------------------------------------
__global__ void __launch_bounds__(NTHREADS, 1)
vq_main_kernel(const float* __restrict__ x,
               const float* __restrict__ cb,
               float* __restrict__ out,
               int n)
{
    extern __shared__ char sm[];
    const u32 su  = smem_u32_base(sm);
    const int tid = threadIdx.x;
    const int w   = tid >> 5;
    const int lid = tid & 31;
    const int wm  = w & 3;        // M chunk: rows wm*32..+32
    const int wn  = w >> 2;       // N half:  codes wn*256..+256

    float* sh_ee  = (float*)(sm + SM_EE);
    float* sh_xx  = (float*)(sm + SM_XX);
    float* sh_xxp = (float*)(sm + SM_XXP);
    float* sh_b   = (float*)(sm + SM_SB);
    float* sh_s   = (float*)(sm + SM_SS);
    int*   sh_i   = (int*)  (sm + SM_SI);

    // ---- codebook: split into B_hi/B_lo fp16 (SW128) + fp32 ||e||^2 ----
    for (int kk = tid; kk < KCODES; kk += NTHREADS) {
        const float4* e4 = (const float4*)(cb + (size_t)kk * VQ_D);
        float a0 = 0.f, a1 = 0.f, a2 = 0.f, a3 = 0.f;
        #pragma unroll
        for (int j = 0; j < 16; j++) {
            float4 v = e4[j];
            __half h0, h1, h2, h3, l0h, l1h, l2h, l3h;
            split16(v.x, h0, l0h); split16(v.y, h1, l1h);
            split16(v.z, h2, l2h); split16(v.w, h3, l3h);
            u32 b = swofs((u32)kk, (u32)j * 8u);
            *(__half2*)(sm + SM_BHI + b)     = __halves2half2(h0, h1);
            *(__half2*)(sm + SM_BHI + b + 4) = __halves2half2(h2, h3);
            *(__half2*)(sm + SM_BLO + b)     = __halves2half2(l0h, l1h);
            *(__half2*)(sm + SM_BLO + b + 4) = __halves2half2(l2h, l3h);
            a0 = fmaf(v.x, v.x, a0); a1 = fmaf(v.y, v.y, a1);
            a2 = fmaf(v.z, v.z, a2); a3 = fmaf(v.w, v.w, a3);
        }
        sh_ee[kk] = __fadd_rn(__fadd_rn(a0, a1), __fadd_rn(a2, a3));
    }
    __syncthreads();

    // per-lane ldmatrix address components
    const u32 arow = (u32)(lid & 7) + ((u32)(lid >> 3) & 1u) * 8u;
    const u32 aoff = ((u32)(lid >> 4) & 1u) * 16u;
    const u32 brow = (u32)(lid & 7) + ((u32)(lid >> 4) & 1u) * 8u;
    const u32 boff = ((u32)(lid >> 3) & 1u) * 16u;
    const int g = lid >> 2, t = lid & 3;

    const int ntiles = n / M_TILE;

    for (int tile = blockIdx.x; tile < ntiles; tile += gridDim.x) {
        // ---- load + split x tile: thread -> row tid/2, d-half tid&1 ----
        {
            const int r = tid >> 1, h = tid & 1;
            const float4* xp = (const float4*)(x + ((size_t)tile * M_TILE + r) * VQ_D + h * 32);
            float p0 = 0.f, p1 = 0.f, p2 = 0.f, p3 = 0.f;
            #pragma unroll
            for (int j = 0; j < 8; j++) {
                float4 v = xp[j];
                __half h0, h1, h2, h3, l0h, l1h, l2h, l3h;
                split16(v.x, h0, l0h); split16(v.y, h1, l1h);
                split16(v.z, h2, l2h); split16(v.w, h3, l3h);
                u32 b = swofs((u32)r, (u32)(h * 64 + j * 8));
                *(__half2*)(sm + SM_AHI + b)     = __halves2half2(h0, h1);
                *(__half2*)(sm + SM_AHI + b + 4) = __halves2half2(h2, h3);
                *(__half2*)(sm + SM_ALO + b)     = __halves2half2(l0h, l1h);
                *(__half2*)(sm + SM_ALO + b + 4) = __halves2half2(l2h, l3h);
                p0 = fmaf(v.x, v.x, p0); p1 = fmaf(v.y, v.y, p1);
                p2 = fmaf(v.z, v.z, p2); p3 = fmaf(v.w, v.w, p3);
            }
            sh_xxp[h * M_TILE + r] = __fadd_rn(__fadd_rn(p0, p1), __fadd_rn(p2, p3));
        }
        __syncthreads();
        if (tid < M_TILE)
            sh_xx[tid] = __fadd_rn(sh_xxp[tid], sh_xxp[M_TILE + tid]);
        __syncthreads();

        // ---- A fragments for this warp's 32 rows (hi & lo), all 4 k-chunks ----
        u32 ahi[2][4][4], alo[2][4][4];
        #pragma unroll
        for (int ms = 0; ms < 2; ms++) {
            #pragma unroll
            for (int k = 0; k < 4; k++) {
                u32 o = swofs((u32)(wm * 32 + ms * 16) + arow, (u32)k * 32u + aoff);
                ldsm_x4(ahi[ms][k][0], ahi[ms][k][1], ahi[ms][k][2], ahi[ms][k][3],
                        su + SM_AHI + o);
                ldsm_x4(alo[ms][k][0], alo[ms][k][1], alo[ms][k][2], alo[ms][k][3],
                        su + SM_ALO + o);
            }
        }

        float xx0 = sh_xx[wm * 32 + g];
        float xx1 = sh_xx[wm * 32 + g + 8];
        float xx2 = sh_xx[wm * 32 + 16 + g];
        float xx3 = sh_xx[wm * 32 + 24 + g];

        float best[4] = {FLT_MAX, FLT_MAX, FLT_MAX, FLT_MAX};
        float sec [4] = {FLT_MAX, FLT_MAX, FLT_MAX, FLT_MAX};
        int   bidx[4] = {0, 0, 0, 0};

        #pragma unroll 1
        for (int chunk = 0; chunk < 4; chunk++) {
            const int nbase = wn * 256 + chunk * 64;
            float acc[2][8][4];
            #pragma unroll
            for (int ms = 0; ms < 2; ms++)
                #pragma unroll
                for (int j = 0; j < 8; j++)
                    #pragma unroll
                    for (int q = 0; q < 4; q++) acc[ms][j][q] = 0.f;

            #pragma unroll
            for (int k = 0; k < 4; k++) {
                u32 bh0[8], bh1[8], bl0[8], bl1[8];
                #pragma unroll
                for (int gi = 0; gi < 4; gi++) {
                    u32 o = swofs((u32)(nbase + gi * 16) + brow, (u32)k * 32u + boff);
                    ldsm_x4(bh0[2*gi], bh1[2*gi], bh0[2*gi+1], bh1[2*gi+1], su + SM_BHI + o);
                    ldsm_x4(bl0[2*gi], bl1[2*gi], bl0[2*gi+1], bl1[2*gi+1], su + SM_BLO + o);
                }
                #pragma unroll
                for (int ms = 0; ms < 2; ms++) {
                    #pragma unroll
                    for (int j = 0; j < 8; j++) {
                        mma16816(acc[ms][j], ahi[ms][k], bh0[j], bh1[j]);  // hi*hi
                        mma16816(acc[ms][j], alo[ms][k], bh0[j], bh1[j]);  // lo*hi
                        mma16816(acc[ms][j], ahi[ms][k], bl0[j], bl1[j]);  // hi*lo
                    }
                }
            }

            // ---- epilogue: distances + top-2 tracking ----
            #pragma unroll
            for (int ms = 0; ms < 2; ms++) {
                const float xa = (ms == 0) ? xx0 : xx2;
                const float xb = (ms == 0) ? xx1 : xx3;
                const int ri = ms * 2;
                #pragma unroll
                for (int j = 0; j < 8; j++) {
                    const int c0 = nbase + j * 8 + 2 * t;
                    float2 ee = *(const float2*)(&sh_ee[c0]);
                    float d00 = fmaf(acc[ms][j][0], -2.f, xa + ee.x);
                    float d01 = fmaf(acc[ms][j][1], -2.f, xa + ee.y);
                    float d10 = fmaf(acc[ms][j][2], -2.f, xb + ee.x);
                    float d11 = fmaf(acc[ms][j][3], -2.f, xb + ee.y);
                    #define UPD(r_, d_, c_) \
                        if ((d_) < best[r_]) { sec[r_] = best[r_]; best[r_] = (d_); bidx[r_] = (c_); } \
                        else sec[r_] = fminf(sec[r_], (d_));
                    UPD(ri,     d00, c0); UPD(ri,     d01, c0 + 1);
                    UPD(ri + 1, d10, c0); UPD(ri + 1, d11, c0 + 1);
                    #undef UPD
                }
            }
        }

        // ---- intra-warp merge over the 4 t-lanes sharing each row ----
        #pragma unroll
        for (int off = 1; off <= 2; off <<= 1) {
            #pragma unroll
            for (int ri = 0; ri < 4; ri++) {
                float ob = __shfl_xor_sync(0xffffffffu, best[ri], off);
                float os = __shfl_xor_sync(0xffffffffu, sec[ri],  off);
                int   oi = __shfl_xor_sync(0xffffffffu, bidx[ri], off);
                bool take = (ob < best[ri]) || (ob == best[ri] && oi < bidx[ri]);
                float loser = take ? best[ri] : ob;
                sec[ri] = fminf(loser, fminf(sec[ri], os));
                if (take) { best[ri] = ob; bidx[ri] = oi; }
            }
        }
        if (t == 0) {
            const int r0 = wm * 32 + g;
            const int rows[4] = {r0, r0 + 8, r0 + 16, r0 + 24};
            #pragma unroll
            for (int ri = 0; ri < 4; ri++) {
                sh_b[wn * M_TILE + rows[ri]] = best[ri];
                sh_s[wn * M_TILE + rows[ri]] = sec[ri];
                sh_i[wn * M_TILE + rows[ri]] = bidx[ri];
            }
        }
        __syncthreads();

        // ---- combine halves, flag near-ties, write outputs ----
        if (tid < M_TILE) {
            float b0 = sh_b[tid], b1 = sh_b[M_TILE + tid];
            float s0 = sh_s[tid], s1 = sh_s[M_TILE + tid];
            int   i0 = sh_i[tid], i1 = sh_i[M_TILE + tid];
            bool take = (b1 < b0) || (b1 == b0 && i1 < i0);
            float fb = take ? b1 : b0;
            int   fi = take ? i1 : i0;
            float fs = fminf(take ? b0 : b1, fminf(s0, s1));

            const size_t grow = (size_t)tile * M_TILE + tid;
            if (fs - fb < TAU) {
                int p = atomicAdd(&g_flag_count, 1);
                g_flag_rows[p] = (int)grow;
            }
            out[grow] = (float)fi;

            const float4* e4  = (const float4*)(cb + (size_t)fi * VQ_D);
            const float4* xr4 = (const float4*)(x + grow * VQ_D);
            float4* q4 = (float4*)(out + (size_t)n + grow * VQ_D);
            float l0 = 0.f, l1 = 0.f, l2 = 0.f, l3 = 0.f;
            #pragma unroll
            for (int j = 0; j < 16; j++) {
                float4 e = e4[j], xv = xr4[j];
                q4[j] = e;
                float d0 = e.x - xv.x, d1 = e.y - xv.y;
                float d2 = e.z - xv.z, d3 = e.w - xv.w;
                l0 = fmaf(d0, d0, l0); l1 = fmaf(d1, d1, l1);
                l2 = fmaf(d2, d2, l2); l3 = fmaf(d3, d3, l3);
            }
            g_loss_row[grow] = __fadd_rn(__fadd_rn(l0, l1), __fadd_rn(l2, l3));
        }
        __syncthreads();   // outputs done before A smem is overwritten
    }
}

// ---------------------------------------------------------------------------
// Kernel 2: exact fp32 fixup of flagged rows (bit-identical to the R8 kernel
// arithmetic that passed with zero argmin flips)
// ---------------------------------------------------------------------------
__global__ void __launch_bounds__(256, 1)
vq_fixup_kernel(const float* __restrict__ x,
                const float* __restrict__ cb,
                float* __restrict__ out,
                int n)
{
    if (*(volatile int*)&g_flag_count == 0) return;

    extern __shared__ float sh[];
    float* sh_cb = sh;                 // 512*64
    float* sh_ee = sh + KCODES * VQ_D; // 512

    const int tid = threadIdx.x;
    {
        const float4* cb4 = (const float4*)cb;
        float4* sh4 = (float4*)sh_cb;
        for (int i = tid; i < KCODES * VQ_D / 4; i += 256) sh4[i] = cb4[i];
    }
    __syncthreads();
    for (int kk = tid; kk < KCODES; kk += 256) {
        const float* e = sh_cb + (size_t)kk * VQ_D;
        float a0 = 0.f, a1 = 0.f, a2 = 0.f, a3 = 0.f;
        #pragma unroll
        for (int j = 0; j < VQ_D; j += 4) {
            a0 = fmaf(e[j+0], e[j+0], a0);
            a1 = fmaf(e[j+1], e[j+1], a1);
            a2 = fmaf(e[j+2], e[j+2], a2);
            a3 = fmaf(e[j+3], e[j+3], a3);
        }
        sh_ee[kk] = __fadd_rn(__fadd_rn(a0, a1), __fadd_rn(a2, a3));
    }
    __syncthreads();

    const int count = g_flag_count;
    for (int i = blockIdx.x * 256 + tid; i < count; i += gridDim.x * 256) {
        const int row = g_flag_rows[i];

        u64 xr[VQ_D / 2];
        const ulonglong2* xp = (const ulonglong2*)(x + (size_t)row * VQ_D);
        #pragma unroll
        for (int j = 0; j < VQ_D / 4; j++) {
            ulonglong2 v = xp[j];
            xr[2*j] = v.x; xr[2*j+1] = v.y;
        }
        float xx;
        {
            float a0 = 0.f, a1 = 0.f, a2 = 0.f, a3 = 0.f;
            #pragma unroll
            for (int j = 0; j < VQ_D / 2; j += 2) {
                float2 fa = u2f(xr[j]), fb = u2f(xr[j+1]);
                a0 = fmaf(fa.x, fa.x, a0); a1 = fmaf(fa.y, fa.y, a1);
                a2 = fmaf(fb.x, fb.x, a2); a3 = fmaf(fb.y, fb.y, a3);
            }
            xx = __fadd_rn(__fadd_rn(a0, a1), __fadd_rn(a2, a3));
        }

        float best = 3.402823466e38f;
        int   bi   = 0;
        const ulonglong2* ebase = (const ulonglong2*)sh_cb;
        #pragma unroll 2
        for (int kk = 0; kk < KCODES; kk++) {
            const ulonglong2* e = ebase + (size_t)kk * (VQ_D / 4);
            u64 a0 = 0ull, a1 = 0ull, a2 = 0ull, a3 = 0ull;
            #pragma unroll
            for (int j = 0; j < VQ_D / 4; j += 2) {
                ulonglong2 e0 = e[j];
                ulonglong2 e1 = e[j + 1];
                a0 = fma2(e0.x, xr[2*j    ], a0);
                a1 = fma2(e0.y, xr[2*j + 1], a1);
                a2 = fma2(e1.x, xr[2*j + 2], a2);
                a3 = fma2(e1.y, xr[2*j + 3], a3);
            }
            u64 s = add2(add2(a0, a1), add2(a2, a3));
            float2 sf = u2f(s);
            float dot  = __fadd_rn(sf.x, sf.y);
            float dist = __fadd_rn(__fadd_rn(xx, sh_ee[kk]),
                                   -__fmul_rn(2.0f, dot));
            if (dist < best) { best = dist; bi = kk; }
        }

        out[row] = (float)bi;
        const float*  e  = sh_cb + (size_t)bi * VQ_D;
        const float4* e4 = (const float4*)e;
        float4* q4 = (float4*)(out + (size_t)n + (size_t)row * VQ_D);
        #pragma unroll
        for (int j = 0; j < VQ_D / 4; j++) q4[j] = e4[j];

        float l0 = 0.f, l1 = 0.f, l2 = 0.f, l3 = 0.f;
        #pragma unroll
        for (int j2 = 0; j2 < VQ_D / 2; j2 += 2) {
            float2 fa = u2f(xr[j2]), fb = u2f(xr[j2 + 1]);
            float d0 = e[2*j2 + 0] - fa.x;
            float d1 = e[2*j2 + 1] - fa.y;
            float d2 = e[2*j2 + 2] - fb.x;
            float d3 = e[2*j2 + 3] - fb.y;
            l0 = fmaf(d0, d0, l0); l1 = fmaf(d1, d1, l1);
            l2 = fmaf(d2, d2, l2); l3 = fmaf(d3, d3, l3);
        }
        g_loss_row[row] = __fadd_rn(__fadd_rn(l0, l1), __fadd_rn(l2, l3));
    }
}

// ---------------------------------------------------------------------------
// Kernels 3+4: deterministic staged loss reduction
// ---------------------------------------------------------------------------
__global__ void vq_reduceA_kernel(int n)
{
    __shared__ double shd[256];
    const int base = blockIdx.x * 2048;
    double s = 0.0;
    #pragma unroll
    for (int j = 0; j < 8; j++) {
        int idx = base + j * 256 + threadIdx.x;
        s += (idx < n) ? (double)g_loss_row[idx] : 0.0;
    }
    shd[threadIdx.x] = s;
    __syncthreads();
    for (int off = 128; off > 0; off >>= 1) {
        if (threadIdx.x < off) shd[threadIdx.x] += shd[threadIdx.x + off];
        __syncthreads();
    }
    if (threadIdx.x == 0) g_partials[blockIdx.x] = shd[0];
}

__global__ void vq_reduceB_kernel(float* __restrict__ out, int n)
{
    __shared__ double shd[256];
    shd[threadIdx.x] = g_partials[threadIdx.x];
    __syncthreads();
    for (int off = 128; off > 0; off >>= 1) {
        if (threadIdx.x < off) shd[threadIdx.x] += shd[threadIdx.x + off];
        __syncthreads();
    }
    if (threadIdx.x == 0) {
        double mean = shd[0] / ((double)n * (double)VQ_D);
        out[(size_t)n + (size_t)n * VQ_D] = (float)(mean * 1.25);
    }
}

// ---------------------------------------------------------------------------
extern "C" void kernel_launch(void* const* d_in, const int* in_sizes, int n_in,
                              void* d_out, int out_size)
{
    const float* x  = (const float*)d_in[0];
    const float* cb = (const float*)d_in[1];
    float* out = (float*)d_out;

    const int n = in_sizes[0] / VQ_D;      // 524288
    const int ntiles = n / M_TILE;         // 4096
    int grid = ntiles < 148 ? ntiles : 148;

    static int attr_done = 0;
    if (!attr_done) {
        cudaFuncSetAttribute(vq_main_kernel,
                             cudaFuncAttributeMaxDynamicSharedMemorySize, SM_TOTAL);
        cudaFuncSetAttribute(vq_fixup_kernel,
                             cudaFuncAttributeMaxDynamicSharedMemorySize,
                             (KCODES * VQ_D + KCODES) * 4);
        attr_done = 1;
    }

    vq_init_kernel<<<1, 1>>>();
    vq_main_kernel<<<grid, NTHREADS, SM_TOTAL>>>(x, cb, out, n);
    vq_fixup_kernel<<<64, 256, (KCODES * VQ_D + KCODES) * 4>>>(x, cb, out, n);
    vq_reduceA_kernel<<<256, 256>>>(n);
    vq_reduceB_kernel<<<1, 256>>>(out, n);
}